// round 15
// baseline (speedup 1.0000x reference)
#include <cuda_runtime.h>
#include <cuda_fp16.h>
#include <cstdint>

#define NV 10000
#define NC 100000
#define B  256
#define NG4 (NC / 4)                 // 25000 groups of 4 clauses, exact
#define GRID_MAIN 1184               // 148 SMs * 8 blocks
#define NSTREAM (GRID_MAIN * 2)      // 2 independent 64-thread streams per block
#define GRID_PREP 2048

// Dual table: row 2v = x, row 2v+1 = 1-x; each row 128 half2 = 512 B.
// 10.24 MB, L2-resident. Both variants rounded directly from fp32 ->
// every literal value carries rel err <= 2^-11 regardless of negation.
__device__ __align__(16) __half2 g_tab[2 * NV * (B / 2)];
// Per literal: half2-offset of its table row: (2v+neg)*128. 1.2 MB.
__device__ __align__(16) unsigned int g_off[NC * 3];

// Fused prologue: detect index dtype, pack literal offsets, build fp16 dual
// table, init d_out. One kernel node.
__global__ void __launch_bounds__(256)
prep_k(const float* __restrict__ input,
       const unsigned int* __restrict__ idx_raw,
       const unsigned int* __restrict__ neg_raw,
       unsigned int* __restrict__ out) {
    __shared__ int s_is64;
    const int tid = threadIdx.x;

    // dtype probe: int64 data (small non-negative) -> odd 32-bit words all 0;
    // int32 data -> odd words are random indices, all-zero ~impossible.
    if (tid < 32) {
        unsigned int acc = 0;
        #pragma unroll
        for (int k = 0; k < 4; ++k) acc |= idx_raw[2 * (tid + 32 * k) + 1];
        acc = __reduce_or_sync(0xFFFFFFFFu, acc);
        if (tid == 0) s_is64 = (acc == 0) ? 1 : 0;
    }
    __syncthreads();
    const int stride = s_is64 ? 2 : 1;

    const int gtid = blockIdx.x * 256 + tid;
    const int gsz  = GRID_PREP * 256;

    if (gtid < B) out[gtid] = 0x7F800000u;   // +inf (d_out poisoned each replay)

    for (int i = gtid; i < NC * 3; i += gsz) {
        unsigned int v = idx_raw[i * stride];
        unsigned int n = neg_raw[i * stride] & 1u;
        if (v >= NV) v = NV - 1;              // defensive clamp: no OOB ever
        g_off[i] = v * 256u + n * 128u;
    }

    for (int i = gtid; i < NV * (B / 2); i += gsz) {
        int v = i >> 7;
        int j = i & 127;
        float2 x = ((const float2*)input)[i];
        g_tab[v * 256 + j]       = __floats2half2_rn(x.x, x.y);
        g_tab[v * 256 + 128 + j] = __floats2half2_rn(1.0f - x.x, 1.0f - x.y);
    }
}

__device__ __forceinline__ __half2 h2(unsigned int u) {
    return *reinterpret_cast<__half2*>(&u);
}
__device__ __forceinline__ __half2 cmax(uint2 a, uint2 b, uint2 c, int hi) {
    unsigned int ua = hi ? a.y : a.x, ub = hi ? b.y : b.x, uc = hi ? c.y : c.x;
    return __hmax2(__hmax2(h2(ua), h2(ub)), h2(uc));
}

// fp16 data in R5's proven instruction shape: per-thread LDG.64, warp reads
// 256 contiguous bytes. 128 threads = two independent 64-thread streams;
// each stream covers the full 256-elem batch (thread owns 4 batch elems)
// and processes its own 4-clause group per iteration: 3x uint4 index loads
// + 12 LDG.64 gathers in flight (24 data regs - the exact footprint that
// batched at the 64-reg budget in R5).
__global__ void __launch_bounds__(128, 8)
cnf_k(unsigned int* __restrict__ out) {
    __shared__ uint4 s_m[2][64];     // per-half partial mins (2 half2 x 64 thr)

    const int t    = threadIdx.x;
    const int half = t >> 6;                 // stream within block
    const int toff = t & 63;                 // thread's slot in the 512B row
    const int sid  = blockIdx.x * 2 + half;  // global stream id

    const __half2 inf2 = __halves2half2(__ushort_as_half(0x7C00), __ushort_as_half(0x7C00));
    __half2 m0 = inf2, m1 = inf2;            // batch elems [4*toff, 4*toff+4)

    for (int g = sid; g < NG4; g += NSTREAM) {
        const uint4* q = (const uint4*)(g_off + g * 12);   // 48B-aligned
        uint4 qa = __ldg(&q[0]);
        uint4 qb = __ldg(&q[1]);
        uint4 qc = __ldg(&q[2]);

        // 12 gathers: uint2 = 2 half2 at half2-offset off + 2*toff
        const int o2 = toff * 2;
        uint2 x0  = __ldg((const uint2*)(g_tab + qa.x + o2));
        uint2 x1  = __ldg((const uint2*)(g_tab + qa.y + o2));
        uint2 x2  = __ldg((const uint2*)(g_tab + qa.z + o2));
        uint2 x3  = __ldg((const uint2*)(g_tab + qa.w + o2));
        uint2 x4  = __ldg((const uint2*)(g_tab + qb.x + o2));
        uint2 x5  = __ldg((const uint2*)(g_tab + qb.y + o2));
        uint2 x6  = __ldg((const uint2*)(g_tab + qb.z + o2));
        uint2 x7  = __ldg((const uint2*)(g_tab + qb.w + o2));
        uint2 x8  = __ldg((const uint2*)(g_tab + qc.x + o2));
        uint2 x9  = __ldg((const uint2*)(g_tab + qc.y + o2));
        uint2 x10 = __ldg((const uint2*)(g_tab + qc.z + o2));
        uint2 x11 = __ldg((const uint2*)(g_tab + qc.w + o2));

        // clause maxes (4 clauses), low and high half2 components
        __half2 c0l = cmax(x0, x1,  x2,  0), c0h = cmax(x0, x1,  x2,  1);
        __half2 c1l = cmax(x3, x4,  x5,  0), c1h = cmax(x3, x4,  x5,  1);
        __half2 c2l = cmax(x6, x7,  x8,  0), c2h = cmax(x6, x7,  x8,  1);
        __half2 c3l = cmax(x9, x10, x11, 0), c3h = cmax(x9, x10, x11, 1);

        m0 = __hmin2(m0, __hmin2(__hmin2(c0l, c1l), __hmin2(c2l, c3l)));
        m1 = __hmin2(m1, __hmin2(__hmin2(c0h, c1h), __hmin2(c2h, c3h)));
    }

    // combine the two streams' partials (both cover the same batch slots)
    uint4 mv;
    mv.x = *reinterpret_cast<unsigned int*>(&m0);
    mv.y = *reinterpret_cast<unsigned int*>(&m1);
    mv.z = 0u; mv.w = 0u;
    s_m[half][toff] = mv;
    __syncthreads();

    if (t < 64) {
        uint4 a = s_m[0][t];
        uint4 b = s_m[1][t];
        __half2 r0 = __hmin2(h2(a.x), h2(b.x));
        __half2 r1 = __hmin2(h2(a.y), h2(b.y));
        // uint bit order == float order for non-negative floats
        atomicMin(&out[4 * t + 0], __float_as_uint(__low2float(r0)));
        atomicMin(&out[4 * t + 1], __float_as_uint(__high2float(r0)));
        atomicMin(&out[4 * t + 2], __float_as_uint(__low2float(r1)));
        atomicMin(&out[4 * t + 3], __float_as_uint(__high2float(r1)));
    }
}

extern "C" void kernel_launch(void* const* d_in, const int* in_sizes, int n_in,
                              void* d_out, int out_size) {
    const float*        input   = (const float*)d_in[0];
    const unsigned int* idx_raw = (const unsigned int*)d_in[1];
    const unsigned int* neg_raw = (const unsigned int*)d_in[2];
    unsigned int*       out     = (unsigned int*)d_out;

    prep_k<<<GRID_PREP, 256>>>(input, idx_raw, neg_raw, out);
    cnf_k<<<GRID_MAIN, 128>>>(out);
}

// round 17
// speedup vs baseline: 1.5877x; 1.5877x over previous
#include <cuda_runtime.h>
#include <cuda_fp16.h>
#include <cstdint>

#define NV 10000
#define NC 100000
#define B  256
#define NG4 (NC / 4)                 // 25000 groups of 4 clauses
#define GRID_MAIN 888                // 148 SMs * 6 blocks (85-reg budget)
#define NWARPS (GRID_MAIN * 4)       // 3552 warp processors
#define GRID_PREP 2048

// Dual table: row 2v = x, row 2v+1 = 1-x; each row 128 half2 = 512 B.
// 10.24 MB, L2-resident. Both variants rounded directly from fp32 ->
// every literal value carries rel err <= 2^-11 regardless of negation.
__device__ __align__(16) __half2 g_tab[2 * NV * (B / 2)];
// Per literal: half2-offset of its table row: (2v+neg)*128. 1.2 MB.
__device__ __align__(16) unsigned int g_off[NC * 3];

// Fused prologue: detect index dtype, pack literal offsets, build fp16 dual
// table, init d_out. One kernel node.
__global__ void __launch_bounds__(256)
prep_k(const float* __restrict__ input,
       const unsigned int* __restrict__ idx_raw,
       const unsigned int* __restrict__ neg_raw,
       unsigned int* __restrict__ out) {
    __shared__ int s_is64;
    const int tid = threadIdx.x;

    // dtype probe: int64 data (small non-negative) -> odd 32-bit words all 0;
    // int32 data -> odd words are random indices, all-zero ~impossible.
    if (tid < 32) {
        unsigned int acc = 0;
        #pragma unroll
        for (int k = 0; k < 4; ++k) acc |= idx_raw[2 * (tid + 32 * k) + 1];
        acc = __reduce_or_sync(0xFFFFFFFFu, acc);
        if (tid == 0) s_is64 = (acc == 0) ? 1 : 0;
    }
    __syncthreads();
    const int stride = s_is64 ? 2 : 1;

    const int gtid = blockIdx.x * 256 + tid;
    const int gsz  = GRID_PREP * 256;

    if (gtid < B) out[gtid] = 0x7F800000u;   // +inf (d_out poisoned each replay)

    for (int i = gtid; i < NC * 3; i += gsz) {
        unsigned int v = idx_raw[i * stride];
        unsigned int n = neg_raw[i * stride] & 1u;
        if (v >= NV) v = NV - 1;              // defensive clamp: no OOB ever
        g_off[i] = v * 256u + n * 128u;
    }

    for (int i = gtid; i < NV * (B / 2); i += gsz) {
        int v = i >> 7;
        int j = i & 127;
        float2 x = ((const float2*)input)[i];
        g_tab[v * 256 + j]       = __floats2half2_rn(x.x, x.y);
        g_tab[v * 256 + 128 + j] = __floats2half2_rn(1.0f - x.x, 1.0f - x.y);
    }
}

__device__ __forceinline__ __half2 h2(unsigned int u) {
    return *reinterpret_cast<__half2*>(&u);
}

// R11's warp-per-row engine, widened: one LDG.128 warp-instruction fetches a
// whole 512 B literal row (lane l -> half2s [4l,4l+4) = batch elems [8l,8l+8)),
// clause max entirely in-lane. 4 clauses per iteration = 12 LDG.128 in
// flight (48 data regs; (128,6) grants an 85-reg budget so ptxas keeps the
// batch). Next group's 3 index-quads prefetched inside the gather window.
__global__ void __launch_bounds__(128, 6)
cnf_k(unsigned int* __restrict__ out) {
    __shared__ uint4 s_m[4][32];     // per-warp partial mins, 2 KB

    const int t    = threadIdx.x;
    const int w    = t >> 5;
    const int lane = t & 31;
    const int gw   = blockIdx.x * 4 + w;

    const __half2 inf2 = __halves2half2(__ushort_as_half(0x7C00), __ushort_as_half(0x7C00));
    __half2 m0 = inf2, m1 = inf2, m2 = inf2, m3 = inf2;

    int g = gw;
    uint4 qa, qb, qc;
    if (g < NG4) {
        const uint4* q = (const uint4*)(g_off + g * 12);   // 48B-aligned
        qa = __ldg(&q[0]); qb = __ldg(&q[1]); qc = __ldg(&q[2]);
    }
    while (g < NG4) {
        // 12 row gathers: one LDG.128 each (lane-sliced full 512B row)
        uint4 xA0 = __ldg((const uint4*)(g_tab + qa.x) + lane);
        uint4 xA1 = __ldg((const uint4*)(g_tab + qa.y) + lane);
        uint4 xA2 = __ldg((const uint4*)(g_tab + qa.z) + lane);
        uint4 xB0 = __ldg((const uint4*)(g_tab + qa.w) + lane);
        uint4 xB1 = __ldg((const uint4*)(g_tab + qb.x) + lane);
        uint4 xB2 = __ldg((const uint4*)(g_tab + qb.y) + lane);
        uint4 xC0 = __ldg((const uint4*)(g_tab + qb.z) + lane);
        uint4 xC1 = __ldg((const uint4*)(g_tab + qb.w) + lane);
        uint4 xC2 = __ldg((const uint4*)(g_tab + qc.x) + lane);
        uint4 xD0 = __ldg((const uint4*)(g_tab + qc.y) + lane);
        uint4 xD1 = __ldg((const uint4*)(g_tab + qc.z) + lane);
        uint4 xD2 = __ldg((const uint4*)(g_tab + qc.w) + lane);

        // prefetch next group's indices while the 12 gathers are in flight
        int gn = g + NWARPS;
        if (gn < NG4) {
            const uint4* qn = (const uint4*)(g_off + gn * 12);
            qa = __ldg(&qn[0]); qb = __ldg(&qn[1]); qc = __ldg(&qn[2]);
        }
        g = gn;

        __half2 cA0 = __hmax2(__hmax2(h2(xA0.x), h2(xA1.x)), h2(xA2.x));
        __half2 cA1 = __hmax2(__hmax2(h2(xA0.y), h2(xA1.y)), h2(xA2.y));
        __half2 cA2 = __hmax2(__hmax2(h2(xA0.z), h2(xA1.z)), h2(xA2.z));
        __half2 cA3 = __hmax2(__hmax2(h2(xA0.w), h2(xA1.w)), h2(xA2.w));
        __half2 cB0 = __hmax2(__hmax2(h2(xB0.x), h2(xB1.x)), h2(xB2.x));
        __half2 cB1 = __hmax2(__hmax2(h2(xB0.y), h2(xB1.y)), h2(xB2.y));
        __half2 cB2 = __hmax2(__hmax2(h2(xB0.z), h2(xB1.z)), h2(xB2.z));
        __half2 cB3 = __hmax2(__hmax2(h2(xB0.w), h2(xB1.w)), h2(xB2.w));
        __half2 cC0 = __hmax2(__hmax2(h2(xC0.x), h2(xC1.x)), h2(xC2.x));
        __half2 cC1 = __hmax2(__hmax2(h2(xC0.y), h2(xC1.y)), h2(xC2.y));
        __half2 cC2 = __hmax2(__hmax2(h2(xC0.z), h2(xC1.z)), h2(xC2.z));
        __half2 cC3 = __hmax2(__hmax2(h2(xC0.w), h2(xC1.w)), h2(xC2.w));
        __half2 cD0 = __hmax2(__hmax2(h2(xD0.x), h2(xD1.x)), h2(xD2.x));
        __half2 cD1 = __hmax2(__hmax2(h2(xD0.y), h2(xD1.y)), h2(xD2.y));
        __half2 cD2 = __hmax2(__hmax2(h2(xD0.z), h2(xD1.z)), h2(xD2.z));
        __half2 cD3 = __hmax2(__hmax2(h2(xD0.w), h2(xD1.w)), h2(xD2.w));

        m0 = __hmin2(m0, __hmin2(__hmin2(cA0, cB0), __hmin2(cC0, cD0)));
        m1 = __hmin2(m1, __hmin2(__hmin2(cA1, cB1), __hmin2(cC1, cD1)));
        m2 = __hmin2(m2, __hmin2(__hmin2(cA2, cB2), __hmin2(cC2, cD2)));
        m3 = __hmin2(m3, __hmin2(__hmin2(cA3, cB3), __hmin2(cC3, cD3)));
    }

    // block reduce: 4 warps hold full-batch partials over the same lanes
    uint4 mv;
    mv.x = *reinterpret_cast<unsigned int*>(&m0);
    mv.y = *reinterpret_cast<unsigned int*>(&m1);
    mv.z = *reinterpret_cast<unsigned int*>(&m2);
    mv.w = *reinterpret_cast<unsigned int*>(&m3);
    s_m[w][lane] = mv;
    __syncthreads();

    // thread t -> half2 column t (lane = t>>2, comp = t&3): conflict-free
    {
        int l = t >> 2, i = t & 3;
        const unsigned int* c0 = (const unsigned int*)&s_m[0][l];
        const unsigned int* c1 = (const unsigned int*)&s_m[1][l];
        const unsigned int* c2 = (const unsigned int*)&s_m[2][l];
        const unsigned int* c3 = (const unsigned int*)&s_m[3][l];
        __half2 r = __hmin2(__hmin2(h2(c0[i]), h2(c1[i])), __hmin2(h2(c2[i]), h2(c3[i])));
        // uint bit order == float order for non-negative floats
        atomicMin(&out[2 * t + 0], __float_as_uint(__low2float(r)));
        atomicMin(&out[2 * t + 1], __float_as_uint(__high2float(r)));
    }
}

extern "C" void kernel_launch(void* const* d_in, const int* in_sizes, int n_in,
                              void* d_out, int out_size) {
    const float*        input   = (const float*)d_in[0];
    const unsigned int* idx_raw = (const unsigned int*)d_in[1];
    const unsigned int* neg_raw = (const unsigned int*)d_in[2];
    unsigned int*       out     = (unsigned int*)d_out;

    prep_k<<<GRID_PREP, 256>>>(input, idx_raw, neg_raw, out);
    cnf_k<<<GRID_MAIN, 128>>>(out);
}